// round 8
// baseline (speedup 1.0000x reference)
#include <cuda_runtime.h>
#include <cuda_bf16.h>
#include <cstdint>

// ---------------------------------------------------------------------------
// PairwiseFairnessLoss: debiased Sinkhorn divergence over 28 subgroup pairs.
// S=8 groups, n=1024 per group, D=256, 116 eps-scaling softmin sweeps.
// Cost matrix stored as uint16 fixed-point (scale 128, range [0,512)) —
// halves the DRAM traffic of the measured 88%-DRAM-bound Sinkhorn loop.
// ---------------------------------------------------------------------------

#define NGROUP 8
#define NPER   1024
#define DDIM   256
#define NPAIR  28
#define NUNIQ  36

// ------------------------- device scratch (no allocs allowed) --------------
__device__ __align__(128) unsigned short Cq[67108864]; // 64 blocks x 1024x1024 u16 = 128MB
__device__ __align__(128) float Gf[NGROUP * NPER * DDIM];
__device__ __align__(128) float sqn[NGROUP * NPER];
__device__ int   permv[NGROUP * NPER];
__device__ __align__(128) float fbuf[2][NPAIR * NPER];
__device__ __align__(128) float gbuf[2][NPAIR * NPER];
__device__ __align__(128) float sbuf[2][NGROUP * NPER];
__device__ __align__(128) float ffin[NPAIR * NPER];
__device__ __align__(128) float gfin[NPAIR * NPER];
__device__ __align__(128) float sfin[NGROUP * NPER];
__device__ float pairloss[NPAIR];

__constant__ int d_II[NPAIR] = {0,0,0,0,0,0,0,1,1,1,1,1,1,2,2,2,2,2,3,3,3,3,4,4,4,5,5,6};
__constant__ int d_JJ[NPAIR] = {1,2,3,4,5,6,7,2,3,4,5,6,7,3,4,5,6,7,4,5,6,7,5,6,7,6,7,7};
__constant__ int d_UGI[NUNIQ] = {0,0,0,0,0,0,0,0, 1,1,1,1,1,1,1, 2,2,2,2,2,2, 3,3,3,3,3, 4,4,4,4, 5,5,5, 6,6, 7};
__constant__ int d_UGJ[NUNIQ] = {0,1,2,3,4,5,6,7, 1,2,3,4,5,6,7, 2,3,4,5,6,7, 3,4,5,6,7, 4,5,6,7, 5,6,7, 6,7, 7};

__device__ __forceinline__ float ex2f(float x) {
    float y; asm("ex2.approx.ftz.f32 %0, %1;" : "=f"(y) : "f"(x)); return y;
}

// ------------------------- stable counting sort by subgroup ----------------
// Replicates jnp.argsort(subgroups, stable=True) for 8 balanced bins.
__global__ void sort_kernel(const int* __restrict__ sg) {
    __shared__ int gbase[NGROUP];
    __shared__ int wcnt[32][NGROUP];
    __shared__ int wbase[32][NGROUP];
    __shared__ int chunkTot[NGROUP];
    int tid = threadIdx.x, w = tid >> 5, lane = tid & 31;
    if (tid < NGROUP) gbase[tid] = 0;
    __syncthreads();
    for (int c = 0; c < 8; c++) {
        int i = c * 1024 + tid;
        int g = sg[i];
        int myrank = 0;
        #pragma unroll
        for (int b = 0; b < NGROUP; b++) {
            unsigned m = __ballot_sync(0xffffffffu, g == b);
            if (g == b) myrank = __popc(m & ((1u << lane) - 1u));
            if (lane == 0) wcnt[w][b] = __popc(m);
        }
        __syncthreads();
        if (tid < NGROUP) {
            int b = tid, run = 0;
            for (int ww = 0; ww < 32; ww++) { wbase[ww][b] = run; run += wcnt[ww][b]; }
            chunkTot[b] = run;
        }
        __syncthreads();
        int dst = g * NPER + gbase[g] + wbase[w][g] + myrank;
        permv[dst] = i;
        __syncthreads();
        if (tid < NGROUP) gbase[tid] += chunkTot[tid];
        __syncthreads();
    }
}

// ------------------------- gather + squared norms --------------------------
__global__ void gather_kernel(const float* __restrict__ feat) {
    int w = threadIdx.x >> 5, lane = threadIdx.x & 31;
    int dst = blockIdx.x * 8 + w;
    int src = permv[dst];
    const float4* frow = (const float4*)(feat + (size_t)src * DDIM);
    float4* grow = (float4*)(Gf + (size_t)dst * DDIM);
    float4 a = frow[lane];
    float4 b = frow[lane + 32];
    grow[lane] = a;
    grow[lane + 32] = b;
    float ss = a.x*a.x + a.y*a.y + a.z*a.z + a.w*a.w
             + b.x*b.x + b.y*b.y + b.z*b.z + b.w*b.w;
    #pragma unroll
    for (int o = 16; o; o >>= 1) ss += __shfl_xor_sync(0xffffffffu, ss, o);
    if (lane == 0) sqn[dst] = ss;
}

// ------------------------- cost GEMM (36 unique blocks) --------------------
// C = max(0.5*sq[a] + 0.5*sq[b] - dot, 0), quantized to u16 with scale 128.
// Saturation (cost >= 512, never observed: max ~434) is numerically inert:
// softmin weights such elements by e^(-C/eps) ~ 0.
__global__ void __launch_bounds__(256) gemm_kernel() {
    int zb = blockIdx.z;
    int gi = d_UGI[zb], gj = d_UGJ[zb];
    int ta = blockIdx.y, tb = blockIdx.x;
    const float* A = Gf + (size_t)(gi * NPER + ta * 128) * DDIM;
    const float* B = Gf + (size_t)(gj * NPER + tb * 128) * DDIM;
    __shared__ __align__(16) float As[16][132];   // 132: 16B-aligned rows (R2 fix)
    __shared__ __align__(16) float Bs[16][132];
    int tid = threadIdx.x;
    int ty = tid >> 4, tx = tid & 15;
    int lr = tid >> 1;
    int lk = (tid & 1) * 8;
    float acc[8][8];
    #pragma unroll
    for (int i = 0; i < 8; i++)
        #pragma unroll
        for (int j = 0; j < 8; j++) acc[i][j] = 0.0f;

    for (int k0 = 0; k0 < DDIM; k0 += 16) {
        float4 a0 = *(const float4*)(A + (size_t)lr * DDIM + k0 + lk);
        float4 a1 = *(const float4*)(A + (size_t)lr * DDIM + k0 + lk + 4);
        float4 b0 = *(const float4*)(B + (size_t)lr * DDIM + k0 + lk);
        float4 b1 = *(const float4*)(B + (size_t)lr * DDIM + k0 + lk + 4);
        __syncthreads();
        As[lk + 0][lr] = a0.x; As[lk + 1][lr] = a0.y; As[lk + 2][lr] = a0.z; As[lk + 3][lr] = a0.w;
        As[lk + 4][lr] = a1.x; As[lk + 5][lr] = a1.y; As[lk + 6][lr] = a1.z; As[lk + 7][lr] = a1.w;
        Bs[lk + 0][lr] = b0.x; Bs[lk + 1][lr] = b0.y; Bs[lk + 2][lr] = b0.z; Bs[lk + 3][lr] = b0.w;
        Bs[lk + 4][lr] = b1.x; Bs[lk + 5][lr] = b1.y; Bs[lk + 6][lr] = b1.z; Bs[lk + 7][lr] = b1.w;
        __syncthreads();
        #pragma unroll
        for (int k = 0; k < 16; k++) {
            float ar[8], br[8];
            *(float4*)(ar)     = *(const float4*)&As[k][ty * 8];
            *(float4*)(ar + 4) = *(const float4*)&As[k][ty * 8 + 4];
            *(float4*)(br)     = *(const float4*)&Bs[k][tx * 8];
            *(float4*)(br + 4) = *(const float4*)&Bs[k][tx * 8 + 4];
            #pragma unroll
            for (int i = 0; i < 8; i++)
                #pragma unroll
                for (int j = 0; j < 8; j++)
                    acc[i][j] = fmaf(ar[i], br[j], acc[i][j]);
        }
    }

    int r0 = ta * 128 + ty * 8;
    int c0 = tb * 128 + tx * 8;
    float sa[8], sb[8];
    #pragma unroll
    for (int i = 0; i < 8; i++) sa[i] = 0.5f * sqn[gi * NPER + r0 + i];
    #pragma unroll
    for (int j = 0; j < 8; j++) sb[j] = 0.5f * sqn[gj * NPER + c0 + j];
    unsigned short* Cb = Cq + ((size_t)(gi * 8 + gj) << 20);
    #pragma unroll
    for (int i = 0; i < 8; i++) {
        unsigned q[8];
        #pragma unroll
        for (int j = 0; j < 8; j++) {
            float c = fmaxf(sa[i] + sb[j] - acc[i][j], 0.0f);
            unsigned v = __float2uint_rn(c * 128.0f);
            q[j] = v > 65535u ? 65535u : v;
        }
        uint4 pk;
        pk.x = q[0] | (q[1] << 16);
        pk.y = q[2] | (q[3] << 16);
        pk.z = q[4] | (q[5] << 16);
        pk.w = q[6] | (q[7] << 16);
        // ushort offset (r0+i)*1024 + c0: c0 multiple of 8 -> 16B aligned
        *(uint4*)(Cb + (size_t)(r0 + i) * NPER + c0) = pk;
    }
}

// ------------------------- transpose off-diagonal blocks (u16) -------------
__global__ void transpose_kernel() {
    int p = blockIdx.z;
    int gi = d_II[p], gj = d_JJ[p];
    const unsigned short* S = Cq + ((size_t)(gi * 8 + gj) << 20);
    unsigned short* D = Cq + ((size_t)(gj * 8 + gi) << 20);
    __shared__ unsigned short t[32][33];
    int x0 = blockIdx.x * 32, y0 = blockIdx.y * 32;
    for (int r = threadIdx.y; r < 32; r += 8)
        t[r][threadIdx.x] = S[(size_t)(y0 + r) * NPER + x0 + threadIdx.x];
    __syncthreads();
    for (int r = threadIdx.y; r < 32; r += 8)
        D[(size_t)(x0 + r) * NPER + y0 + threadIdx.x] = t[threadIdx.x][r];
}

// ------------------------- zero initial potentials -------------------------
__global__ void zero_kernel() {
    int i = blockIdx.x * 256 + threadIdx.x;
    if (i < NPAIR * NPER) { fbuf[0][i] = 0.0f; gbuf[0][i] = 0.0f; }
    if (i < NGROUP * NPER) sbuf[0][i] = 0.0f;
}

// ------------------------- one Sinkhorn step -------------------------------
// grid (128, 64): y = task-matrix [0..27]=f, [28..55]=g, [56..63]=s.
// Warp-per-row, 1024-element logsumexp over u16-quantized cost.
__global__ void __launch_bounds__(256) step_kernel(float eps, int src, int fin) {
    int t = blockIdx.y;
    const unsigned short* Cb; const float* h; float* outp; const float* savg = nullptr;
    if (t < 28) {
        int gi = d_II[t], gj = d_JJ[t];
        Cb = Cq + ((size_t)(gi * 8 + gj) << 20);
        h = gbuf[src] + t * NPER;
        outp = (fin ? ffin : fbuf[src ^ 1]) + t * NPER;
    } else if (t < 56) {
        int q = t - 28;
        int gi = d_II[q], gj = d_JJ[q];
        Cb = Cq + ((size_t)(gj * 8 + gi) << 20);
        h = fbuf[src] + q * NPER;
        outp = (fin ? gfin : gbuf[src ^ 1]) + q * NPER;
    } else {
        int g = t - 56;
        Cb = Cq + ((size_t)(g * 9) << 20);
        h = sbuf[src] + g * NPER;
        savg = h;
        outp = (fin ? sfin : sbuf[src ^ 1]) + g * NPER;
    }

    __shared__ __align__(16) float hs[1024];
    const float kk  = (1.0f / eps) * 1.4426950408889634f;  // log2(e)/eps
    const float nsk = -kk * (1.0f / 128.0f);               // dequant * (-k), log2 units
    int tid = threadIdx.x;
    {
        float4 hv = ((const float4*)h)[tid];
        ((float4*)hs)[tid] = make_float4(hv.x * kk, hv.y * kk, hv.z * kk, hv.w * kk);
    }
    __syncthreads();

    int w = tid >> 5, lane = tid & 31;
    int row = (blockIdx.x << 3) + w;
    // row * 1024 ushorts = row * 2048 bytes -> 16B aligned uint4 view
    const uint4* Cr = (const uint4*)(Cb + ((size_t)row << 10));

    // issue all 4 global loads up front (MLP=4), then unpack
    uint4 cv[4];
    #pragma unroll
    for (int kc = 0; kc < 4; kc++) cv[kc] = Cr[(kc << 5) + lane];

    float u[32];
    float M = -3.402823466e38f;
    #pragma unroll
    for (int kc = 0; kc < 4; kc++) {
        int e0 = ((kc << 5) + lane) << 3;                 // element base, multiple of 8
        const float4* hp = (const float4*)&hs[e0];        // 32B-aligned
        float4 h0 = hp[0], h1 = hp[1];
        uint4 c = cv[kc];
        float* uu = &u[kc * 8];
        uu[0] = fmaf((float)(c.x & 0xFFFFu), nsk, h0.x);
        uu[1] = fmaf((float)(c.x >> 16),     nsk, h0.y);
        uu[2] = fmaf((float)(c.y & 0xFFFFu), nsk, h0.z);
        uu[3] = fmaf((float)(c.y >> 16),     nsk, h0.w);
        uu[4] = fmaf((float)(c.z & 0xFFFFu), nsk, h1.x);
        uu[5] = fmaf((float)(c.z >> 16),     nsk, h1.y);
        uu[6] = fmaf((float)(c.w & 0xFFFFu), nsk, h1.z);
        uu[7] = fmaf((float)(c.w >> 16),     nsk, h1.w);
        #pragma unroll
        for (int j = 0; j < 8; j++) M = fmaxf(M, uu[j]);
    }
    #pragma unroll
    for (int o = 16; o; o >>= 1) M = fmaxf(M, __shfl_xor_sync(0xffffffffu, M, o));

    float s0 = 0.f, s1 = 0.f, s2 = 0.f, s3 = 0.f;
    #pragma unroll
    for (int kc = 0; kc < 4; kc++) {
        float* uu = &u[kc * 8];
        s0 += ex2f(uu[0] - M); s1 += ex2f(uu[1] - M);
        s2 += ex2f(uu[2] - M); s3 += ex2f(uu[3] - M);
        s0 += ex2f(uu[4] - M); s1 += ex2f(uu[5] - M);
        s2 += ex2f(uu[6] - M); s3 += ex2f(uu[7] - M);
    }
    float sum = (s0 + s1) + (s2 + s3);
    #pragma unroll
    for (int o = 16; o; o >>= 1) sum += __shfl_xor_sync(0xffffffffu, sum, o);

    if (lane == 0) {
        // M in log2 units: lse_ln = M*ln2 + log(sum); softmin = -eps*(lse - ln 1024)
        float lse = fmaf(M, 0.6931471805599453f, logf(sum));
        float res = -eps * (lse - 6.931471805599453f);
        if (savg && !fin) res = 0.5f * (savg[row] + res);
        outp[row] = res;
    }
}

// ------------------------- loss reductions ---------------------------------
__global__ void loss_kernel() {
    int p = blockIdx.x;
    int gi = d_II[p], gj = d_JJ[p];
    float sum = 0.0f;
    for (int i = threadIdx.x; i < NPER; i += 256) {
        sum += (ffin[p * NPER + i] - sfin[gi * NPER + i])
             + (gfin[p * NPER + i] - sfin[gj * NPER + i]);
    }
    __shared__ float red[256];
    red[threadIdx.x] = sum;
    __syncthreads();
    for (int s = 128; s; s >>= 1) {
        if (threadIdx.x < s) red[threadIdx.x] += red[threadIdx.x + s];
        __syncthreads();
    }
    if (threadIdx.x == 0) pairloss[p] = red[0] * (1.0f / 1024.0f);
}

__global__ void final_kernel(float* __restrict__ out, int out_size) {
    int lane = threadIdx.x;
    float v = (lane < NPAIR) ? pairloss[lane] : 0.0f;
    float tot = v;
    #pragma unroll
    for (int o = 16; o; o >>= 1) tot += __shfl_xor_sync(0xffffffffu, tot, o);
    tot *= (1.0f / 28.0f);
    if (out_size >= 29) {
        if (lane == 0) out[0] = tot;
        if (lane < NPAIR) out[1 + lane] = v;
        for (int i = 29 + lane; i < out_size; i += 32) out[i] = 0.0f;
    } else if (out_size == 28) {
        if (lane < NPAIR) out[lane] = v;
    } else {
        if (lane == 0 && out_size >= 1) out[0] = tot;
        for (int i = 1 + lane; i < out_size; i += 32) out[i] = 0.0f;
    }
}

// ------------------------- host driver -------------------------------------
extern "C" void kernel_launch(void* const* d_in, const int* in_sizes, int n_in,
                              void* d_out, int out_size) {
    const float* feat = (const float*)d_in[0];
    const int* sg = (const int*)d_in[1];
    float* out = (float*)d_out;
    (void)in_sizes; (void)n_in;

    sort_kernel<<<1, 1024>>>(sg);
    gather_kernel<<<1024, 256>>>(feat);
    {
        dim3 g(8, 8, NUNIQ);
        gemm_kernel<<<g, 256>>>();
    }
    {
        dim3 g(32, 32, NPAIR);
        transpose_kernel<<<g, dim3(32, 8)>>>();
    }
    zero_kernel<<<112, 256>>>();

    // eps schedule: replicate the Python float64 loop exactly, cast f32 per step
    dim3 sg2(128, 64);
    double eps = 256.0;                 // float(D)
    const double tgt = 1e-4 * 1e-4;     // BLUR**P_NORM = 1e-8
    const double ratio = 0.9 * 0.9;     // SCALING**P_NORM
    int src = 0;
    while (eps > tgt) {
        step_kernel<<<sg2, 256>>>((float)eps, src, 0);
        src ^= 1;
        eps *= ratio;
    }
    step_kernel<<<sg2, 256>>>((float)tgt, src, 0);
    src ^= 1;
    // final extrapolation: plain softmin for all three parts at eps_target
    step_kernel<<<sg2, 256>>>((float)tgt, src, 1);

    loss_kernel<<<NPAIR, 256>>>();
    final_kernel<<<1, 32>>>(out, out_size);
}

// round 11
// speedup vs baseline: 1.0882x; 1.0882x over previous
#include <cuda_runtime.h>
#include <cuda_bf16.h>
#include <cstdint>

// ---------------------------------------------------------------------------
// PairwiseFairnessLoss: debiased Sinkhorn divergence over 28 subgroup pairs.
// S=8 groups, n=1024 per group, D=256, 116 eps-scaling softmin sweeps.
// Cost: u16 fixed-point (scale 128), ONLY the 36 unique blocks (72MB) so the
// whole working set fits in the 126MB L2 — g-updates read columns in place.
// ---------------------------------------------------------------------------

#define NGROUP 8
#define NPER   1024
#define DDIM   256
#define NPAIR  28
#define NUNIQ  36

// ------------------------- device scratch (no allocs allowed) --------------
__device__ __align__(128) unsigned short Cq[37748736]; // 36 blocks x 1024x1024 u16 = 72MB
__device__ __align__(128) float Gf[NGROUP * NPER * DDIM];
__device__ __align__(128) float sqn[NGROUP * NPER];
__device__ int   permv[NGROUP * NPER];
__device__ __align__(128) float fbuf[2][NPAIR * NPER];
__device__ __align__(128) float gbuf[2][NPAIR * NPER];
__device__ __align__(128) float sbuf[2][NGROUP * NPER];
__device__ __align__(128) float ffin[NPAIR * NPER];
__device__ __align__(128) float gfin[NPAIR * NPER];
__device__ __align__(128) float sfin[NGROUP * NPER];
__device__ float pairloss[NPAIR];

__constant__ int d_II[NPAIR] = {0,0,0,0,0,0,0,1,1,1,1,1,1,2,2,2,2,2,3,3,3,3,4,4,4,5,5,6};
__constant__ int d_JJ[NPAIR] = {1,2,3,4,5,6,7,2,3,4,5,6,7,3,4,5,6,7,4,5,6,7,5,6,7,6,7,7};
// enumeration of the 36 unique (gi<=gj) blocks, in gemm z-order
__constant__ int d_UGI[NUNIQ] = {0,0,0,0,0,0,0,0, 1,1,1,1,1,1,1, 2,2,2,2,2,2, 3,3,3,3,3, 4,4,4,4, 5,5,5, 6,6, 7};
__constant__ int d_UGJ[NUNIQ] = {0,1,2,3,4,5,6,7, 1,2,3,4,5,6,7, 2,3,4,5,6,7, 3,4,5,6,7, 4,5,6,7, 5,6,7, 6,7, 7};
// pair p=(II[p],JJ[p]) -> unique-block index; diagonal g -> unique-block index
__constant__ int d_PB[NPAIR] = {1,2,3,4,5,6,7, 9,10,11,12,13,14, 16,17,18,19,20, 22,23,24,25, 27,28,29, 31,32, 34};
__constant__ int d_DB[NGROUP] = {0,8,15,21,26,30,33,35};

__device__ __forceinline__ float ex2f(float x) {
    float y; asm("ex2.approx.ftz.f32 %0, %1;" : "=f"(y) : "f"(x)); return y;
}

// ------------------------- stable counting sort by subgroup ----------------
__global__ void sort_kernel(const int* __restrict__ sg) {
    __shared__ int gbase[NGROUP];
    __shared__ int wcnt[32][NGROUP];
    __shared__ int wbase[32][NGROUP];
    __shared__ int chunkTot[NGROUP];
    int tid = threadIdx.x, w = tid >> 5, lane = tid & 31;
    if (tid < NGROUP) gbase[tid] = 0;
    __syncthreads();
    for (int c = 0; c < 8; c++) {
        int i = c * 1024 + tid;
        int g = sg[i];
        int myrank = 0;
        #pragma unroll
        for (int b = 0; b < NGROUP; b++) {
            unsigned m = __ballot_sync(0xffffffffu, g == b);
            if (g == b) myrank = __popc(m & ((1u << lane) - 1u));
            if (lane == 0) wcnt[w][b] = __popc(m);
        }
        __syncthreads();
        if (tid < NGROUP) {
            int b = tid, run = 0;
            for (int ww = 0; ww < 32; ww++) { wbase[ww][b] = run; run += wcnt[ww][b]; }
            chunkTot[b] = run;
        }
        __syncthreads();
        int dst = g * NPER + gbase[g] + wbase[w][g] + myrank;
        permv[dst] = i;
        __syncthreads();
        if (tid < NGROUP) gbase[tid] += chunkTot[tid];
        __syncthreads();
    }
}

// ------------------------- gather + squared norms --------------------------
__global__ void gather_kernel(const float* __restrict__ feat) {
    int w = threadIdx.x >> 5, lane = threadIdx.x & 31;
    int dst = blockIdx.x * 8 + w;
    int src = permv[dst];
    const float4* frow = (const float4*)(feat + (size_t)src * DDIM);
    float4* grow = (float4*)(Gf + (size_t)dst * DDIM);
    float4 a = frow[lane];
    float4 b = frow[lane + 32];
    grow[lane] = a;
    grow[lane + 32] = b;
    float ss = a.x*a.x + a.y*a.y + a.z*a.z + a.w*a.w
             + b.x*b.x + b.y*b.y + b.z*b.z + b.w*b.w;
    #pragma unroll
    for (int o = 16; o; o >>= 1) ss += __shfl_xor_sync(0xffffffffu, ss, o);
    if (lane == 0) sqn[dst] = ss;
}

// ------------------------- cost GEMM (36 unique blocks) --------------------
// C = max(0.5*sq[a] + 0.5*sq[b] - dot, 0), quantized to u16 with scale 128.
__global__ void __launch_bounds__(256) gemm_kernel() {
    int zb = blockIdx.z;
    int gi = d_UGI[zb], gj = d_UGJ[zb];
    int ta = blockIdx.y, tb = blockIdx.x;
    const float* A = Gf + (size_t)(gi * NPER + ta * 128) * DDIM;
    const float* B = Gf + (size_t)(gj * NPER + tb * 128) * DDIM;
    __shared__ __align__(16) float As[16][132];   // 132: 16B-aligned rows (R2 fix)
    __shared__ __align__(16) float Bs[16][132];
    int tid = threadIdx.x;
    int ty = tid >> 4, tx = tid & 15;
    int lr = tid >> 1;
    int lk = (tid & 1) * 8;
    float acc[8][8];
    #pragma unroll
    for (int i = 0; i < 8; i++)
        #pragma unroll
        for (int j = 0; j < 8; j++) acc[i][j] = 0.0f;

    for (int k0 = 0; k0 < DDIM; k0 += 16) {
        float4 a0 = *(const float4*)(A + (size_t)lr * DDIM + k0 + lk);
        float4 a1 = *(const float4*)(A + (size_t)lr * DDIM + k0 + lk + 4);
        float4 b0 = *(const float4*)(B + (size_t)lr * DDIM + k0 + lk);
        float4 b1 = *(const float4*)(B + (size_t)lr * DDIM + k0 + lk + 4);
        __syncthreads();
        As[lk + 0][lr] = a0.x; As[lk + 1][lr] = a0.y; As[lk + 2][lr] = a0.z; As[lk + 3][lr] = a0.w;
        As[lk + 4][lr] = a1.x; As[lk + 5][lr] = a1.y; As[lk + 6][lr] = a1.z; As[lk + 7][lr] = a1.w;
        Bs[lk + 0][lr] = b0.x; Bs[lk + 1][lr] = b0.y; Bs[lk + 2][lr] = b0.z; Bs[lk + 3][lr] = b0.w;
        Bs[lk + 4][lr] = b1.x; Bs[lk + 5][lr] = b1.y; Bs[lk + 6][lr] = b1.z; Bs[lk + 7][lr] = b1.w;
        __syncthreads();
        #pragma unroll
        for (int k = 0; k < 16; k++) {
            float ar[8], br[8];
            *(float4*)(ar)     = *(const float4*)&As[k][ty * 8];
            *(float4*)(ar + 4) = *(const float4*)&As[k][ty * 8 + 4];
            *(float4*)(br)     = *(const float4*)&Bs[k][tx * 8];
            *(float4*)(br + 4) = *(const float4*)&Bs[k][tx * 8 + 4];
            #pragma unroll
            for (int i = 0; i < 8; i++)
                #pragma unroll
                for (int j = 0; j < 8; j++)
                    acc[i][j] = fmaf(ar[i], br[j], acc[i][j]);
        }
    }

    int r0 = ta * 128 + ty * 8;
    int c0 = tb * 128 + tx * 8;
    float sa[8], sb[8];
    #pragma unroll
    for (int i = 0; i < 8; i++) sa[i] = 0.5f * sqn[gi * NPER + r0 + i];
    #pragma unroll
    for (int j = 0; j < 8; j++) sb[j] = 0.5f * sqn[gj * NPER + c0 + j];
    unsigned short* Cb = Cq + ((size_t)zb << 20);
    #pragma unroll
    for (int i = 0; i < 8; i++) {
        unsigned q[8];
        #pragma unroll
        for (int j = 0; j < 8; j++) {
            float c = fmaxf(sa[i] + sb[j] - acc[i][j], 0.0f);
            unsigned v = __float2uint_rn(c * 128.0f);
            q[j] = v > 65535u ? 65535u : v;
        }
        uint4 pk;
        pk.x = q[0] | (q[1] << 16);
        pk.y = q[2] | (q[3] << 16);
        pk.z = q[4] | (q[5] << 16);
        pk.w = q[6] | (q[7] << 16);
        *(uint4*)(Cb + (size_t)(r0 + i) * NPER + c0) = pk;
    }
}

// ------------------------- zero initial potentials -------------------------
__global__ void zero_kernel() {
    int i = blockIdx.x * 256 + threadIdx.x;
    if (i < NPAIR * NPER) { fbuf[0][i] = 0.0f; gbuf[0][i] = 0.0f; }
    if (i < NGROUP * NPER) sbuf[0][i] = 0.0f;
}

// ------------------------- one Sinkhorn step -------------------------------
// grid (128, 64): y = task [0..27]=f (row LSE), [28..55]=g (COLUMN LSE over
// the same unique block — no transposed copy), [56..63]=s (row LSE, diag).
__global__ void __launch_bounds__(256) step_kernel(float eps, int src, int fin) {
    int t = blockIdx.y;
    const unsigned short* Cb; const float* h; float* outp;
    const float* savg = nullptr; bool colmode = false;
    if (t < 28) {
        Cb = Cq + ((size_t)d_PB[t] << 20);
        h = gbuf[src] + t * NPER;
        outp = (fin ? ffin : fbuf[src ^ 1]) + t * NPER;
    } else if (t < 56) {
        if (blockIdx.x >= 32) return;     // block-uniform, before any sync
        int q = t - 28;
        colmode = true;
        Cb = Cq + ((size_t)d_PB[q] << 20);
        h = fbuf[src] + q * NPER;
        outp = (fin ? gfin : gbuf[src ^ 1]) + q * NPER;
    } else {
        int g = t - 56;
        Cb = Cq + ((size_t)d_DB[g] << 20);
        h = sbuf[src] + g * NPER;
        savg = h;
        outp = (fin ? sfin : sbuf[src ^ 1]) + g * NPER;
    }

    __shared__ __align__(16) float hs[1024];
    __shared__ float pm[8][32];
    __shared__ float ps[8][32];
    const float kk  = (1.0f / eps) * 1.4426950408889634f;  // log2(e)/eps
    const float nsk = -kk * (1.0f / 128.0f);               // dequant * (-k), log2 units
    int tid = threadIdx.x;
    {
        float4 hv = ((const float4*)h)[tid];
        ((float4*)hs)[tid] = make_float4(hv.x * kk, hv.y * kk, hv.z * kk, hv.w * kk);
    }
    __syncthreads();

    int w = tid >> 5, lane = tid & 31;

    if (!colmode) {
        // ---------- row-wise LSE (f and s): proven R8 path ----------
        int row = (blockIdx.x << 3) + w;
        const uint4* Cr = (const uint4*)(Cb + ((size_t)row << 10));
        uint4 cv[4];
        #pragma unroll
        for (int kc = 0; kc < 4; kc++) cv[kc] = Cr[(kc << 5) + lane];

        float u[32];
        float M = -3.402823466e38f;
        #pragma unroll
        for (int kc = 0; kc < 4; kc++) {
            int e0 = ((kc << 5) + lane) << 3;
            const float4* hp = (const float4*)&hs[e0];
            float4 h0 = hp[0], h1 = hp[1];
            uint4 c = cv[kc];
            float* uu = &u[kc * 8];
            uu[0] = fmaf((float)(c.x & 0xFFFFu), nsk, h0.x);
            uu[1] = fmaf((float)(c.x >> 16),     nsk, h0.y);
            uu[2] = fmaf((float)(c.y & 0xFFFFu), nsk, h0.z);
            uu[3] = fmaf((float)(c.y >> 16),     nsk, h0.w);
            uu[4] = fmaf((float)(c.z & 0xFFFFu), nsk, h1.x);
            uu[5] = fmaf((float)(c.z >> 16),     nsk, h1.y);
            uu[6] = fmaf((float)(c.w & 0xFFFFu), nsk, h1.z);
            uu[7] = fmaf((float)(c.w >> 16),     nsk, h1.w);
            #pragma unroll
            for (int j = 0; j < 8; j++) M = fmaxf(M, uu[j]);
        }
        #pragma unroll
        for (int o = 16; o; o >>= 1) M = fmaxf(M, __shfl_xor_sync(0xffffffffu, M, o));

        float s0 = 0.f, s1 = 0.f, s2 = 0.f, s3 = 0.f;
        #pragma unroll
        for (int kc = 0; kc < 4; kc++) {
            float* uu = &u[kc * 8];
            s0 += ex2f(uu[0] - M); s1 += ex2f(uu[1] - M);
            s2 += ex2f(uu[2] - M); s3 += ex2f(uu[3] - M);
            s0 += ex2f(uu[4] - M); s1 += ex2f(uu[5] - M);
            s2 += ex2f(uu[6] - M); s3 += ex2f(uu[7] - M);
        }
        float sum = (s0 + s1) + (s2 + s3);
        #pragma unroll
        for (int o = 16; o; o >>= 1) sum += __shfl_xor_sync(0xffffffffu, sum, o);

        if (lane == 0) {
            float lse = fmaf(M, 0.6931471805599453f, logf(sum));
            float res = -eps * (lse - 6.931471805599453f);
            if (savg && !fin) res = 0.5f * (savg[row] + res);
            outp[row] = res;
        }
    } else {
        // ---------- column-wise LSE (g): lanes = 32 consecutive columns ----
        // warp w handles rows [w*128, w*128+128) of columns j0..j0+31.
        int j = (blockIdx.x << 5) + lane;                // this lane's column
        const unsigned short* Cp = Cb + ((size_t)(w << 7) << 10) + j;
        const float* fsp = hs + (w << 7);                // scaled f for my rows
        float m = -3.402823466e38f;
        float s0 = 0.f, s1 = 0.f, s2 = 0.f, s3 = 0.f;
        for (int r = 0; r < 128; r += 8) {
            float v[8];
            #pragma unroll
            for (int k2 = 0; k2 < 8; k2++)
                v[k2] = fmaf((float)Cp[(size_t)(r + k2) << 10], nsk, fsp[r + k2]);
            float lm = fmaxf(fmaxf(fmaxf(v[0], v[1]), fmaxf(v[2], v[3])),
                             fmaxf(fmaxf(v[4], v[5]), fmaxf(v[6], v[7])));
            if (lm > m) {                 // rare after warmup; first iter: s*0=0
                float rsc = ex2f(m - lm);
                s0 *= rsc; s1 *= rsc; s2 *= rsc; s3 *= rsc;
                m = lm;
            }
            s0 += ex2f(v[0] - m); s1 += ex2f(v[1] - m);
            s2 += ex2f(v[2] - m); s3 += ex2f(v[3] - m);
            s0 += ex2f(v[4] - m); s1 += ex2f(v[5] - m);
            s2 += ex2f(v[6] - m); s3 += ex2f(v[7] - m);
        }
        pm[w][lane] = m;
        ps[w][lane] = (s0 + s1) + (s2 + s3);
        __syncthreads();
        if (w == 0) {
            float M = pm[0][lane];
            #pragma unroll
            for (int k2 = 1; k2 < 8; k2++) M = fmaxf(M, pm[k2][lane]);
            float S = 0.0f;
            #pragma unroll
            for (int k2 = 0; k2 < 8; k2++) S += ps[k2][lane] * ex2f(pm[k2][lane] - M);
            float lse = fmaf(M, 0.6931471805599453f, logf(S));
            outp[j] = -eps * (lse - 6.931471805599453f);
        }
    }
}

// ------------------------- loss reductions ---------------------------------
__global__ void loss_kernel() {
    int p = blockIdx.x;
    int gi = d_II[p], gj = d_JJ[p];
    float sum = 0.0f;
    for (int i = threadIdx.x; i < NPER; i += 256) {
        sum += (ffin[p * NPER + i] - sfin[gi * NPER + i])
             + (gfin[p * NPER + i] - sfin[gj * NPER + i]);
    }
    __shared__ float red[256];
    red[threadIdx.x] = sum;
    __syncthreads();
    for (int s = 128; s; s >>= 1) {
        if (threadIdx.x < s) red[threadIdx.x] += red[threadIdx.x + s];
        __syncthreads();
    }
    if (threadIdx.x == 0) pairloss[p] = red[0] * (1.0f / 1024.0f);
}

__global__ void final_kernel(float* __restrict__ out, int out_size) {
    int lane = threadIdx.x;
    float v = (lane < NPAIR) ? pairloss[lane] : 0.0f;
    float tot = v;
    #pragma unroll
    for (int o = 16; o; o >>= 1) tot += __shfl_xor_sync(0xffffffffu, tot, o);
    tot *= (1.0f / 28.0f);
    if (out_size >= 29) {
        if (lane == 0) out[0] = tot;
        if (lane < NPAIR) out[1 + lane] = v;
        for (int i = 29 + lane; i < out_size; i += 32) out[i] = 0.0f;
    } else if (out_size == 28) {
        if (lane < NPAIR) out[lane] = v;
    } else {
        if (lane == 0 && out_size >= 1) out[0] = tot;
        for (int i = 1 + lane; i < out_size; i += 32) out[i] = 0.0f;
    }
}

// ------------------------- host driver -------------------------------------
extern "C" void kernel_launch(void* const* d_in, const int* in_sizes, int n_in,
                              void* d_out, int out_size) {
    const float* feat = (const float*)d_in[0];
    const int* sg = (const int*)d_in[1];
    float* out = (float*)d_out;
    (void)in_sizes; (void)n_in;

    sort_kernel<<<1, 1024>>>(sg);
    gather_kernel<<<1024, 256>>>(feat);
    {
        dim3 g(8, 8, NUNIQ);
        gemm_kernel<<<g, 256>>>();
    }
    zero_kernel<<<112, 256>>>();

    // eps schedule: replicate the Python float64 loop exactly, cast f32 per step
    dim3 sg2(128, 64);
    double eps = 256.0;                 // float(D)
    const double tgt = 1e-4 * 1e-4;     // BLUR**P_NORM = 1e-8
    const double ratio = 0.9 * 0.9;     // SCALING**P_NORM
    int src = 0;
    while (eps > tgt) {
        step_kernel<<<sg2, 256>>>((float)eps, src, 0);
        src ^= 1;
        eps *= ratio;
    }
    step_kernel<<<sg2, 256>>>((float)tgt, src, 0);
    src ^= 1;
    // final extrapolation: plain softmin for all three parts at eps_target
    step_kernel<<<sg2, 256>>>((float)tgt, src, 1);

    loss_kernel<<<NPAIR, 256>>>();
    final_kernel<<<1, 32>>>(out, out_size);
}